// round 11
// baseline (speedup 1.0000x reference)
#include <cuda_runtime.h>
#include <cuda_bf16.h>
#include <cstdint>

#define N_NODES 100000
#define HID 128
#define E_MAX 1600000
#define NB_SCAN 98            /* ceil(100000/1024) */

// Scratch (allocation-free rule: __device__ globals).
static __device__ float g_bufA[N_NODES * HID];
static __device__ int   g_count[N_NODES];
static __device__ int   g_cursor[N_NODES];
static __device__ int   g_off[N_NODES + 1];
static __device__ int   g_bsum[128];
static __device__ int   g_eid[E_MAX];
static __device__ int   g_is64;

// ---------------------------------------------------------------------------
// Helpers
// ---------------------------------------------------------------------------
__device__ __forceinline__ uint32_t smem_u32(const void* p) {
    uint32_t a;
    asm("{ .reg .u64 t; cvta.to.shared.u64 t, %1; cvt.u32.u64 %0, t; }"
        : "=r"(a) : "l"(p));
    return a;
}

__device__ __forceinline__ void hilo2(float x, float y, uint32_t& h, uint32_t& l) {
    __nv_bfloat162 bh = __floats2bfloat162_rn(x, y);
    float rx = x - __bfloat162float(bh.x);
    float ry = y - __bfloat162float(bh.y);
    __nv_bfloat162 bl = __floats2bfloat162_rn(rx, ry);
    h = *(uint32_t*)&bh;
    l = *(uint32_t*)&bl;
}

__device__ __forceinline__ long long edge_node(const void* idxp, int e, int is64) {
    return is64 ? ((const long long*)idxp)[e] : (long long)((const int*)idxp)[e];
}

#define LDSM_X4(r0, r1, r2, r3, a)                                            \
    asm volatile("ldmatrix.sync.aligned.m8n8.x4.shared.b16 {%0,%1,%2,%3},[%4];" \
                 : "=r"(r0), "=r"(r1), "=r"(r2), "=r"(r3) : "r"(a))

#define MMA_BF16(d, a0, a1, a2, a3, b0, b1)                                   \
    asm volatile(                                                             \
        "mma.sync.aligned.m16n8k16.row.col.f32.bf16.bf16.f32 "                \
        "{%0,%1,%2,%3}, {%4,%5,%6,%7}, {%8,%9}, {%0,%1,%2,%3};"               \
        : "+f"((d)[0]), "+f"((d)[1]), "+f"((d)[2]), "+f"((d)[3])              \
        : "r"(a0), "r"(a1), "r"(a2), "r"(a3), "r"(b0), "r"(b1))

// ---------------------------------------------------------------------------
// Detect idx dtype (int64 vs silently-int32 reference)
// ---------------------------------------------------------------------------
__global__ void detect_kernel(const int* __restrict__ idx32) {
    if (threadIdx.x == 0 && blockIdx.x == 0) {
        int is64 = 1;
        #pragma unroll 1
        for (int k = 0; k < 64; ++k) {
            int lo = idx32[2 * k];
            int hi = idx32[2 * k + 1];
            if (hi != 0 || lo < 0 || lo >= N_NODES) { is64 = 0; break; }
        }
        g_is64 = is64;
    }
}

// ---------------------------------------------------------------------------
// Counting sort of edges by destination node
// ---------------------------------------------------------------------------
__global__ void zero_cnt_kernel() {
    int i = blockIdx.x * blockDim.x + threadIdx.x;
    int s = gridDim.x * blockDim.x;
    for (; i < N_NODES; i += s) g_count[i] = 0;
}

__global__ void hist_kernel(const void* __restrict__ idxp, int E) {
    const int is64 = g_is64;
    int e = blockIdx.x * blockDim.x + threadIdx.x;
    int s = gridDim.x * blockDim.x;
    for (; e < E; e += s)
        atomicAdd(&g_count[(int)edge_node(idxp, e, is64)], 1);
}

__global__ __launch_bounds__(1024) void scan1_kernel() {
    __shared__ int sm[1024];
    int t = threadIdx.x;
    int i = blockIdx.x * 1024 + t;
    int v = (i < N_NODES) ? g_count[i] : 0;
    sm[t] = v;
    __syncthreads();
    #pragma unroll
    for (int o = 1; o < 1024; o <<= 1) {
        int u = (t >= o) ? sm[t - o] : 0;
        __syncthreads();
        sm[t] += u;
        __syncthreads();
    }
    if (i < N_NODES) g_off[i] = sm[t] - v;        // exclusive within block
    if (t == 1023) g_bsum[blockIdx.x] = sm[1023]; // block total
}

__global__ void scan2_kernel() {
    __shared__ int sm[128];
    int t = threadIdx.x;
    int v = (t < NB_SCAN) ? g_bsum[t] : 0;
    sm[t] = v;
    __syncthreads();
    #pragma unroll
    for (int o = 1; o < 128; o <<= 1) {
        int u = (t >= o) ? sm[t - o] : 0;
        __syncthreads();
        sm[t] += u;
        __syncthreads();
    }
    if (t < NB_SCAN) g_bsum[t] = sm[t] - v;       // exclusive block offsets
}

__global__ void scan3_kernel(int E) {
    int i = blockIdx.x * blockDim.x + threadIdx.x;
    int s = gridDim.x * blockDim.x;
    for (; i < N_NODES; i += s) {
        g_off[i] += g_bsum[i >> 10];
        g_cursor[i] = 0;
    }
    if (blockIdx.x == 0 && threadIdx.x == 0) g_off[N_NODES] = E;
}

__global__ void scatter_kernel(const void* __restrict__ idxp, int E) {
    const int is64 = g_is64;
    int e = blockIdx.x * blockDim.x + threadIdx.x;
    int s = gridDim.x * blockDim.x;
    for (; e < E; e += s) {
        int node = (int)edge_node(idxp, e, is64);
        int pos = g_off[node] + atomicAdd(&g_cursor[node], 1);
        g_eid[pos] = e;
    }
}

// ---------------------------------------------------------------------------
// Gather: one warp per node; accumulate gated messages in regs, write once.
// gated[e,h] = (sum_r rbf[e,r] * W_rbf[h,r]) * x[e,h]
// ---------------------------------------------------------------------------
__global__ __launch_bounds__(256) void gather_kernel(
    const float* __restrict__ x,
    const float* __restrict__ rbf,
    const float* __restrict__ W_rbf,
    float* __restrict__ acc)
{
    __shared__ float ws[6][HID];   // W_rbf transposed: ws[r][h]
    const int tid = threadIdx.x;
    for (int t = tid; t < 6 * HID; t += blockDim.x)
        ws[t % 6][t / 6] = W_rbf[t];
    __syncthreads();

    const int lane = tid & 31;
    const int warp = tid >> 5;
    const int h0   = lane * 4;

    float4 w[6];
    #pragma unroll
    for (int r = 0; r < 6; ++r) w[r] = *(const float4*)&ws[r][h0];

    const int n = blockIdx.x * 8 + warp;   // grid sized so n < N_NODES always
    const int beg = g_off[n];
    const int end = g_off[n + 1];

    float4 s = make_float4(0.f, 0.f, 0.f, 0.f);

    for (int j0 = beg; j0 < end; j0 += 32) {
        const int cnt = min(32, end - j0);
        int myeid = (lane < cnt) ? g_eid[j0 + lane] : 0;

        // software pipeline: prefetch edge t+1 while computing edge t
        int eid = __shfl_sync(0xFFFFFFFFu, myeid, 0);
        float4 xv = *(const float4*)(x + (size_t)eid * HID + h0);
        const float2* rp = (const float2*)(rbf + (size_t)eid * 6);
        float2 r01 = rp[0], r23 = rp[1], r45 = rp[2];

        for (int t = 0; t < cnt; ++t) {
            float4 xc = xv;
            float2 a = r01, b = r23, c = r45;
            if (t + 1 < cnt) {
                int e2 = __shfl_sync(0xFFFFFFFFu, myeid, t + 1);
                xv = *(const float4*)(x + (size_t)e2 * HID + h0);
                const float2* rp2 = (const float2*)(rbf + (size_t)e2 * 6);
                r01 = rp2[0]; r23 = rp2[1]; r45 = rp2[2];
            }
            float4 p;
            p.x = w[0].x * a.x; p.y = w[0].y * a.x;
            p.z = w[0].z * a.x; p.w = w[0].w * a.x;
            #define ACCR(RV, RI) \
                p.x = fmaf(RV, w[RI].x, p.x); p.y = fmaf(RV, w[RI].y, p.y); \
                p.z = fmaf(RV, w[RI].z, p.z); p.w = fmaf(RV, w[RI].w, p.w);
            ACCR(a.y, 1) ACCR(b.x, 2) ACCR(b.y, 3) ACCR(c.x, 4) ACCR(c.y, 5)
            #undef ACCR
            s.x = fmaf(p.x, xc.x, s.x); s.y = fmaf(p.y, xc.y, s.y);
            s.z = fmaf(p.z, xc.z, s.z); s.w = fmaf(p.w, xc.w, s.w);
        }
    }
    *(float4*)(acc + (size_t)n * HID + h0) = s;
}

// ---------------------------------------------------------------------------
// Fused 4-layer MLP on mma.sync (bf16 hi/lo compensated, fp32 accumulate).
// Tile: 256 rows x 128 cols per CTA; 16 warps, warp w owns rows [16w,16w+16).
// B ldmatrix x4 (two n-tiles per load): 34 -> 18 LDSM/k-step.
// ---------------------------------------------------------------------------
#define ST       136
#define A_BYTES  (256 * ST * 2)
#define W_BYTES  (128 * ST * 2)
#define SM_A_HI  0
#define SM_A_LO  (A_BYTES)
#define SM_W_HI  (2 * A_BYTES)
#define SM_W_LO  (2 * A_BYTES + W_BYTES)
#define SMEM_TOT (2 * A_BYTES + 2 * W_BYTES)   /* 208896 */

__device__ __forceinline__ void convert_W(uint32_t sb, const float* __restrict__ W,
                                          int w, int L) {
    int r  = w * 8 + (L >> 2);
    int cb = (L & 3) * 4;
    #pragma unroll
    for (int g = 0; g < 8; ++g) {
        int c = cb + g * 16;
        float4 v = *(const float4*)(W + (size_t)r * 128 + c);
        uint32_t h0, l0, h1, l1;
        hilo2(v.x, v.y, h0, l0);
        hilo2(v.z, v.w, h1, l1);
        uint32_t off = (uint32_t)(r * ST + c) * 2;
        asm volatile("st.shared.v2.b32 [%0], {%1,%2};"
                     :: "r"(sb + SM_W_HI + off), "r"(h0), "r"(h1));
        asm volatile("st.shared.v2.b32 [%0], {%1,%2};"
                     :: "r"(sb + SM_W_LO + off), "r"(l0), "r"(l1));
    }
}

__global__ void __launch_bounds__(512, 1) mlp_fused_kernel(
    const float* __restrict__ in,
    const float* __restrict__ W1, const float* __restrict__ b1,
    const float* __restrict__ W2, const float* __restrict__ b2,
    const float* __restrict__ W3, const float* __restrict__ b3,
    const float* __restrict__ Wo,
    float* __restrict__ out)
{
    extern __shared__ char smem[];
    uint32_t sb = smem_u32(smem);
    const int tid  = threadIdx.x;
    const int w    = tid >> 5;
    const int L    = tid & 31;
    const int row0 = blockIdx.x * 256;

    // ---- Load A tile, fp32 -> bf16 hi/lo, zero-pad OOB rows ----
    {
        int r  = w * 16 + (L >> 1);
        int gr = row0 + r;
        int cb = (L & 1) * 64;
        #pragma unroll
        for (int g = 0; g < 8; ++g) {
            int c = cb + g * 8;
            float v[8];
            if (gr < N_NODES) {
                float4 u0 = *(const float4*)(in + (size_t)gr * 128 + c);
                float4 u1 = *(const float4*)(in + (size_t)gr * 128 + c + 4);
                v[0]=u0.x; v[1]=u0.y; v[2]=u0.z; v[3]=u0.w;
                v[4]=u1.x; v[5]=u1.y; v[6]=u1.z; v[7]=u1.w;
            } else {
                #pragma unroll
                for (int i = 0; i < 8; ++i) v[i] = 0.f;
            }
            uint32_t h[4], l[4];
            #pragma unroll
            for (int i = 0; i < 4; ++i) hilo2(v[2*i], v[2*i+1], h[i], l[i]);
            uint32_t off = (uint32_t)(r * ST + c) * 2;
            asm volatile("st.shared.v4.b32 [%0], {%1,%2,%3,%4};"
                         :: "r"(sb + SM_A_HI + off),
                            "r"(h[0]), "r"(h[1]), "r"(h[2]), "r"(h[3]));
            asm volatile("st.shared.v4.b32 [%0], {%1,%2,%3,%4};"
                         :: "r"(sb + SM_A_LO + off),
                            "r"(l[0]), "r"(l[1]), "r"(l[2]), "r"(l[3]));
        }
    }
    convert_W(sb, W1, w, L);
    __syncthreads();

    const float* Wn[3] = {W2, W3, Wo};
    const float* Bp[3] = {b1, b2, b3};

    // A-fragment base (row = 16w + L%16, col-block = (L/16)*8)
    const uint32_t aOff = (uint32_t)((w * 16 + (L & 15)) * ST + ((L >> 4) << 3)) * 2;
    // B x4 lane address: matrices 0,1 = n-tile 2p (cols k / k+8);
    // matrices 2,3 = n-tile 2p+1. row = (L&7) + (L>=16 ? 8 : 0), col = ((L>>3)&1)*8
    const uint32_t bLane4 =
        (uint32_t)((((L & 7) + ((L >> 4) << 3)) * ST) + (((L >> 3) & 1) << 3)) * 2;

    #pragma unroll 1
    for (int Layer = 0; Layer < 4; ++Layer) {
        const float* bias = (Layer < 3) ? Bp[Layer] : nullptr;
        const int p2 = 2 * (L & 3);

        float acc[64];
        #pragma unroll
        for (int nt = 0; nt < 16; ++nt) {
            float b0 = 0.f, c1 = 0.f;
            if (bias) { b0 = bias[nt * 8 + p2]; c1 = bias[nt * 8 + p2 + 1]; }
            acc[nt*4 + 0] = b0; acc[nt*4 + 1] = c1;
            acc[nt*4 + 2] = b0; acc[nt*4 + 3] = c1;
        }

        #pragma unroll
        for (int k = 0; k < 128; k += 16) {
            uint32_t ah0, ah1, ah2, ah3, al0, al1, al2, al3;
            LDSM_X4(ah0, ah1, ah2, ah3, sb + SM_A_HI + aOff + k * 2);
            LDSM_X4(al0, al1, al2, al3, sb + SM_A_LO + aOff + k * 2);
            #pragma unroll
            for (int p = 0; p < 8; ++p) {
                uint32_t bAddr = bLane4 + (uint32_t)(p * 16 * ST + k) * 2;
                uint32_t bh0, bh1, bh2, bh3, bl0, bl1, bl2, bl3;
                LDSM_X4(bh0, bh1, bh2, bh3, sb + SM_W_HI + bAddr);
                LDSM_X4(bl0, bl1, bl2, bl3, sb + SM_W_LO + bAddr);
                MMA_BF16(acc + (2*p  )*4, ah0, ah1, ah2, ah3, bh0, bh1);
                MMA_BF16(acc + (2*p  )*4, al0, al1, al2, al3, bh0, bh1);
                MMA_BF16(acc + (2*p  )*4, ah0, ah1, ah2, ah3, bl0, bl1);
                MMA_BF16(acc + (2*p+1)*4, ah0, ah1, ah2, ah3, bh2, bh3);
                MMA_BF16(acc + (2*p+1)*4, al0, al1, al2, al3, bh2, bh3);
                MMA_BF16(acc + (2*p+1)*4, ah0, ah1, ah2, ah3, bl2, bl3);
            }
        }

        const int r0 = w * 16 + (L >> 2);
        if (Layer < 3) {
            #pragma unroll
            for (int nt = 0; nt < 16; ++nt) {
                int c = nt * 8 + p2;
                float s[4];
                #pragma unroll
                for (int j = 0; j < 4; ++j) {
                    float v = acc[nt*4 + j];
                    s[j] = v / (1.f + __expf(-v));
                }
                uint32_t h0, l0, h1, l1;
                hilo2(s[0], s[1], h0, l0);
                hilo2(s[2], s[3], h1, l1);
                uint32_t o0 = (uint32_t)(r0 * ST + c) * 2;
                uint32_t o1 = (uint32_t)((r0 + 8) * ST + c) * 2;
                asm volatile("st.shared.b32 [%0], %1;" :: "r"(sb + SM_A_HI + o0), "r"(h0));
                asm volatile("st.shared.b32 [%0], %1;" :: "r"(sb + SM_A_LO + o0), "r"(l0));
                asm volatile("st.shared.b32 [%0], %1;" :: "r"(sb + SM_A_HI + o1), "r"(h1));
                asm volatile("st.shared.b32 [%0], %1;" :: "r"(sb + SM_A_LO + o1), "r"(l1));
            }
            __syncthreads();
            convert_W(sb, Wn[Layer], w, L);
            __syncthreads();
        } else {
            int gr0 = row0 + r0;
            int gr1 = gr0 + 8;
            #pragma unroll
            for (int nt = 0; nt < 16; ++nt) {
                int c = nt * 8 + p2;
                if (gr0 < N_NODES)
                    *(float2*)(out + (size_t)gr0 * 128 + c) =
                        make_float2(acc[nt*4 + 0], acc[nt*4 + 1]);
                if (gr1 < N_NODES)
                    *(float2*)(out + (size_t)gr1 * 128 + c) =
                        make_float2(acc[nt*4 + 2], acc[nt*4 + 3]);
            }
        }
    }
}

// ---------------------------------------------------------------------------
// Launch: detect -> sort edges by node -> gather -> fused MLP
// ---------------------------------------------------------------------------
extern "C" void kernel_launch(void* const* d_in, const int* in_sizes, int n_in,
                              void* d_out, int out_size) {
    const float* x     = (const float*)d_in[0];
    const float* rbf   = (const float*)d_in[1];
    const void*  idx   = d_in[2];
    const float* W_rbf = (const float*)d_in[3];
    const float* W1    = (const float*)d_in[4];
    const float* b1    = (const float*)d_in[5];
    const float* W2    = (const float*)d_in[6];
    const float* b2    = (const float*)d_in[7];
    const float* W3    = (const float*)d_in[8];
    const float* b3    = (const float*)d_in[9];
    const float* W_out = (const float*)d_in[10];
    float* out = (float*)d_out;

    const int E = in_sizes[0] / HID;

    float* bufA = nullptr;
    cudaGetSymbolAddress((void**)&bufA, g_bufA);

    cudaFuncSetAttribute(mlp_fused_kernel,
                         cudaFuncAttributeMaxDynamicSharedMemorySize, SMEM_TOT);

    detect_kernel<<<1, 32>>>((const int*)idx);
    zero_cnt_kernel<<<128, 256>>>();
    hist_kernel<<<4096, 256>>>(idx, E);
    scan1_kernel<<<NB_SCAN, 1024>>>();
    scan2_kernel<<<1, 128>>>();
    scan3_kernel<<<128, 256>>>(E);
    scatter_kernel<<<4096, 256>>>(idx, E);
    gather_kernel<<<N_NODES / 8, 256>>>(x, rbf, W_rbf, bufA);

    const int gtiles = (N_NODES + 255) / 256;
    mlp_fused_kernel<<<gtiles, 512, SMEM_TOT>>>(bufA, W1, b1, W2, b2, W3, b3,
                                                W_out, out);
}

// round 13
// speedup vs baseline: 1.0971x; 1.0971x over previous
#include <cuda_runtime.h>
#include <cuda_bf16.h>
#include <cstdint>

#define N_NODES 100000
#define HID 128
#define E_MAX 1600000
#define NB_SCAN 98            /* ceil(100000/1024) */

// Scratch (allocation-free rule: __device__ globals).
static __device__ float g_bufA[N_NODES * HID];
static __device__ int   g_count[N_NODES];
static __device__ int   g_cursor[N_NODES];
static __device__ int   g_off[N_NODES + 1];
static __device__ int   g_bsum[128];
static __device__ int   g_eid[E_MAX];
static __device__ int   g_is64;

// ---------------------------------------------------------------------------
// Helpers
// ---------------------------------------------------------------------------
__device__ __forceinline__ uint32_t smem_u32(const void* p) {
    uint32_t a;
    asm("{ .reg .u64 t; cvta.to.shared.u64 t, %1; cvt.u32.u64 %0, t; }"
        : "=r"(a) : "l"(p));
    return a;
}

__device__ __forceinline__ void hilo2(float x, float y, uint32_t& h, uint32_t& l) {
    __nv_bfloat162 bh = __floats2bfloat162_rn(x, y);
    float rx = x - __bfloat162float(bh.x);
    float ry = y - __bfloat162float(bh.y);
    __nv_bfloat162 bl = __floats2bfloat162_rn(rx, ry);
    h = *(uint32_t*)&bh;
    l = *(uint32_t*)&bl;
}

__device__ __forceinline__ long long edge_node(const void* idxp, int e, int is64) {
    return is64 ? ((const long long*)idxp)[e] : (long long)((const int*)idxp)[e];
}

#define LDSM_X4(r0, r1, r2, r3, a)                                            \
    asm volatile("ldmatrix.sync.aligned.m8n8.x4.shared.b16 {%0,%1,%2,%3},[%4];" \
                 : "=r"(r0), "=r"(r1), "=r"(r2), "=r"(r3) : "r"(a))

#define MMA_BF16(d, a0, a1, a2, a3, b0, b1)                                   \
    asm volatile(                                                             \
        "mma.sync.aligned.m16n8k16.row.col.f32.bf16.bf16.f32 "                \
        "{%0,%1,%2,%3}, {%4,%5,%6,%7}, {%8,%9}, {%0,%1,%2,%3};"               \
        : "+f"((d)[0]), "+f"((d)[1]), "+f"((d)[2]), "+f"((d)[3])              \
        : "r"(a0), "r"(a1), "r"(a2), "r"(a3), "r"(b0), "r"(b1))

// ---------------------------------------------------------------------------
// Zero counters + detect idx dtype (merged)
// ---------------------------------------------------------------------------
__global__ void zero_detect_kernel(const int* __restrict__ idx32) {
    int i = blockIdx.x * blockDim.x + threadIdx.x;
    int s = gridDim.x * blockDim.x;
    for (; i < N_NODES; i += s) g_count[i] = 0;
    if (blockIdx.x == 0 && threadIdx.x == 0) {
        int is64 = 1;
        #pragma unroll 1
        for (int k = 0; k < 64; ++k) {
            int lo = idx32[2 * k];
            int hi = idx32[2 * k + 1];
            if (hi != 0 || lo < 0 || lo >= N_NODES) { is64 = 0; break; }
        }
        g_is64 = is64;
    }
}

// ---------------------------------------------------------------------------
// Counting sort of edges by destination node
// ---------------------------------------------------------------------------
__global__ void hist_kernel(const void* __restrict__ idxp, int E) {
    const int is64 = g_is64;
    int e = blockIdx.x * blockDim.x + threadIdx.x;
    int s = gridDim.x * blockDim.x;
    for (; e < E; e += s)
        atomicAdd(&g_count[(int)edge_node(idxp, e, is64)], 1);
}

__global__ __launch_bounds__(1024) void scan1_kernel() {
    __shared__ int sm[1024];
    int t = threadIdx.x;
    int i = blockIdx.x * 1024 + t;
    int v = (i < N_NODES) ? g_count[i] : 0;
    sm[t] = v;
    __syncthreads();
    #pragma unroll
    for (int o = 1; o < 1024; o <<= 1) {
        int u = (t >= o) ? sm[t - o] : 0;
        __syncthreads();
        sm[t] += u;
        __syncthreads();
    }
    if (i < N_NODES) g_off[i] = sm[t] - v;        // exclusive within block
    if (t == 1023) g_bsum[blockIdx.x] = sm[1023]; // block total
}

// Fused scan2+scan3: each 256-thread block covers one 256-aligned node range,
// so all its nodes share the same 1024-chunk; thread 0 sums the needed prefix
// of the 98 block totals (<=97 adds), broadcasts via smem.
__global__ void scan23_kernel(int E) {
    __shared__ int S;
    const int b = blockIdx.x;
    const int i = b * 256 + threadIdx.x;
    if (threadIdx.x == 0) {
        int c = (b * 256) >> 10;        // chunk index, uniform for the block
        int s = 0;
        for (int k = 0; k < c; ++k) s += g_bsum[k];
        S = s;
    }
    __syncthreads();
    if (i < N_NODES) {
        g_off[i] += S;
        g_cursor[i] = 0;
    }
    if (i == 0) g_off[N_NODES] = E;
}

__global__ void scatter_kernel(const void* __restrict__ idxp, int E) {
    const int is64 = g_is64;
    int e = blockIdx.x * blockDim.x + threadIdx.x;
    int s = gridDim.x * blockDim.x;
    for (; e < E; e += s) {
        int node = (int)edge_node(idxp, e, is64);
        int pos = g_off[node] + atomicAdd(&g_cursor[node], 1);
        g_eid[pos] = e;
    }
}

// ---------------------------------------------------------------------------
// Gather: one warp per node; 4 edges in flight per iteration (MLP=4) to cover
// the ~600-cyc load latency that bound the R11 version. Write each row once.
// gated[e,h] = (sum_r rbf[e,r] * W_rbf[h,r]) * x[e,h]
// ---------------------------------------------------------------------------
struct EdgeRegs { float4 xv; float2 a, b, c; };

__device__ __forceinline__ void acc_edge(const float4 w[6], const EdgeRegs& er,
                                         float4& s) {
    float4 p;
    p.x = w[0].x * er.a.x; p.y = w[0].y * er.a.x;
    p.z = w[0].z * er.a.x; p.w = w[0].w * er.a.x;
    #define ACCR(RV, RI) \
        p.x = fmaf(RV, w[RI].x, p.x); p.y = fmaf(RV, w[RI].y, p.y); \
        p.z = fmaf(RV, w[RI].z, p.z); p.w = fmaf(RV, w[RI].w, p.w);
    ACCR(er.a.y, 1) ACCR(er.b.x, 2) ACCR(er.b.y, 3) ACCR(er.c.x, 4) ACCR(er.c.y, 5)
    #undef ACCR
    s.x = fmaf(p.x, er.xv.x, s.x); s.y = fmaf(p.y, er.xv.y, s.y);
    s.z = fmaf(p.z, er.xv.z, s.z); s.w = fmaf(p.w, er.xv.w, s.w);
}

__device__ __forceinline__ void load_edge(const float* __restrict__ x,
                                          const float* __restrict__ rbf,
                                          int eid, int h0, EdgeRegs& er) {
    er.xv = *(const float4*)(x + (size_t)eid * HID + h0);
    const float2* q = (const float2*)(rbf + (size_t)eid * 6);
    er.a = q[0]; er.b = q[1]; er.c = q[2];
}

__global__ __launch_bounds__(256) void gather_kernel(
    const float* __restrict__ x,
    const float* __restrict__ rbf,
    const float* __restrict__ W_rbf,
    float* __restrict__ acc)
{
    __shared__ float ws[6][HID];   // W_rbf transposed: ws[r][h]
    const int tid = threadIdx.x;
    for (int t = tid; t < 6 * HID; t += blockDim.x)
        ws[t % 6][t / 6] = W_rbf[t];
    __syncthreads();

    const int lane = tid & 31;
    const int warp = tid >> 5;
    const int h0   = lane * 4;

    float4 w[6];
    #pragma unroll
    for (int r = 0; r < 6; ++r) w[r] = *(const float4*)&ws[r][h0];

    const int n = blockIdx.x * 8 + warp;   // grid sized so n < N_NODES always
    const int beg = g_off[n];
    const int end = g_off[n + 1];

    float4 s = make_float4(0.f, 0.f, 0.f, 0.f);

    for (int j0 = beg; j0 < end; j0 += 32) {
        const int cnt = min(32, end - j0);
        int myeid = (lane < cnt) ? g_eid[j0 + lane] : 0;

        int t = 0;
        for (; t + 4 <= cnt; t += 4) {
            int e0 = __shfl_sync(0xFFFFFFFFu, myeid, t);
            int e1 = __shfl_sync(0xFFFFFFFFu, myeid, t + 1);
            int e2 = __shfl_sync(0xFFFFFFFFu, myeid, t + 2);
            int e3 = __shfl_sync(0xFFFFFFFFu, myeid, t + 3);
            EdgeRegs er0, er1, er2, er3;
            load_edge(x, rbf, e0, h0, er0);   // 4 independent x-row loads:
            load_edge(x, rbf, e1, h0, er1);   // MLP=4, issued back-to-back
            load_edge(x, rbf, e2, h0, er2);
            load_edge(x, rbf, e3, h0, er3);
            acc_edge(w, er0, s);
            acc_edge(w, er1, s);
            acc_edge(w, er2, s);
            acc_edge(w, er3, s);
        }
        for (; t < cnt; ++t) {
            int e0 = __shfl_sync(0xFFFFFFFFu, myeid, t);
            EdgeRegs er;
            load_edge(x, rbf, e0, h0, er);
            acc_edge(w, er, s);
        }
    }
    *(float4*)(acc + (size_t)n * HID + h0) = s;
}

// ---------------------------------------------------------------------------
// Fused 4-layer MLP on mma.sync (bf16 hi/lo compensated, fp32 accumulate).
// Tile: 256 rows x 128 cols per CTA; 16 warps, warp w owns rows [16w,16w+16).
// B ldmatrix x4 (two n-tiles per load): 18 LDSM/k-step.
// ---------------------------------------------------------------------------
#define ST       136
#define A_BYTES  (256 * ST * 2)
#define W_BYTES  (128 * ST * 2)
#define SM_A_HI  0
#define SM_A_LO  (A_BYTES)
#define SM_W_HI  (2 * A_BYTES)
#define SM_W_LO  (2 * A_BYTES + W_BYTES)
#define SMEM_TOT (2 * A_BYTES + 2 * W_BYTES)   /* 208896 */

__device__ __forceinline__ void convert_W(uint32_t sb, const float* __restrict__ W,
                                          int w, int L) {
    int r  = w * 8 + (L >> 2);
    int cb = (L & 3) * 4;
    #pragma unroll
    for (int g = 0; g < 8; ++g) {
        int c = cb + g * 16;
        float4 v = *(const float4*)(W + (size_t)r * 128 + c);
        uint32_t h0, l0, h1, l1;
        hilo2(v.x, v.y, h0, l0);
        hilo2(v.z, v.w, h1, l1);
        uint32_t off = (uint32_t)(r * ST + c) * 2;
        asm volatile("st.shared.v2.b32 [%0], {%1,%2};"
                     :: "r"(sb + SM_W_HI + off), "r"(h0), "r"(h1));
        asm volatile("st.shared.v2.b32 [%0], {%1,%2};"
                     :: "r"(sb + SM_W_LO + off), "r"(l0), "r"(l1));
    }
}

__global__ void __launch_bounds__(512, 1) mlp_fused_kernel(
    const float* __restrict__ in,
    const float* __restrict__ W1, const float* __restrict__ b1,
    const float* __restrict__ W2, const float* __restrict__ b2,
    const float* __restrict__ W3, const float* __restrict__ b3,
    const float* __restrict__ Wo,
    float* __restrict__ out)
{
    extern __shared__ char smem[];
    uint32_t sb = smem_u32(smem);
    const int tid  = threadIdx.x;
    const int w    = tid >> 5;
    const int L    = tid & 31;
    const int row0 = blockIdx.x * 256;

    // ---- Load A tile, fp32 -> bf16 hi/lo, zero-pad OOB rows ----
    {
        int r  = w * 16 + (L >> 1);
        int gr = row0 + r;
        int cb = (L & 1) * 64;
        #pragma unroll
        for (int g = 0; g < 8; ++g) {
            int c = cb + g * 8;
            float v[8];
            if (gr < N_NODES) {
                float4 u0 = *(const float4*)(in + (size_t)gr * 128 + c);
                float4 u1 = *(const float4*)(in + (size_t)gr * 128 + c + 4);
                v[0]=u0.x; v[1]=u0.y; v[2]=u0.z; v[3]=u0.w;
                v[4]=u1.x; v[5]=u1.y; v[6]=u1.z; v[7]=u1.w;
            } else {
                #pragma unroll
                for (int i = 0; i < 8; ++i) v[i] = 0.f;
            }
            uint32_t h[4], l[4];
            #pragma unroll
            for (int i = 0; i < 4; ++i) hilo2(v[2*i], v[2*i+1], h[i], l[i]);
            uint32_t off = (uint32_t)(r * ST + c) * 2;
            asm volatile("st.shared.v4.b32 [%0], {%1,%2,%3,%4};"
                         :: "r"(sb + SM_A_HI + off),
                            "r"(h[0]), "r"(h[1]), "r"(h[2]), "r"(h[3]));
            asm volatile("st.shared.v4.b32 [%0], {%1,%2,%3,%4};"
                         :: "r"(sb + SM_A_LO + off),
                            "r"(l[0]), "r"(l[1]), "r"(l[2]), "r"(l[3]));
        }
    }
    convert_W(sb, W1, w, L);
    __syncthreads();

    const float* Wn[3] = {W2, W3, Wo};
    const float* Bp[3] = {b1, b2, b3};

    // A-fragment base (row = 16w + L%16, col-block = (L/16)*8)
    const uint32_t aOff = (uint32_t)((w * 16 + (L & 15)) * ST + ((L >> 4) << 3)) * 2;
    // B x4 lane address: matrices 0,1 = n-tile 2p (cols k / k+8);
    // matrices 2,3 = n-tile 2p+1. row = (L&7) + (L>=16 ? 8 : 0), col = ((L>>3)&1)*8
    const uint32_t bLane4 =
        (uint32_t)((((L & 7) + ((L >> 4) << 3)) * ST) + (((L >> 3) & 1) << 3)) * 2;

    #pragma unroll 1
    for (int Layer = 0; Layer < 4; ++Layer) {
        const float* bias = (Layer < 3) ? Bp[Layer] : nullptr;
        const int p2 = 2 * (L & 3);

        float acc[64];
        #pragma unroll
        for (int nt = 0; nt < 16; ++nt) {
            float b0 = 0.f, c1 = 0.f;
            if (bias) { b0 = bias[nt * 8 + p2]; c1 = bias[nt * 8 + p2 + 1]; }
            acc[nt*4 + 0] = b0; acc[nt*4 + 1] = c1;
            acc[nt*4 + 2] = b0; acc[nt*4 + 3] = c1;
        }

        #pragma unroll
        for (int k = 0; k < 128; k += 16) {
            uint32_t ah0, ah1, ah2, ah3, al0, al1, al2, al3;
            LDSM_X4(ah0, ah1, ah2, ah3, sb + SM_A_HI + aOff + k * 2);
            LDSM_X4(al0, al1, al2, al3, sb + SM_A_LO + aOff + k * 2);
            #pragma unroll
            for (int p = 0; p < 8; ++p) {
                uint32_t bAddr = bLane4 + (uint32_t)(p * 16 * ST + k) * 2;
                uint32_t bh0, bh1, bh2, bh3, bl0, bl1, bl2, bl3;
                LDSM_X4(bh0, bh1, bh2, bh3, sb + SM_W_HI + bAddr);
                LDSM_X4(bl0, bl1, bl2, bl3, sb + SM_W_LO + bAddr);
                MMA_BF16(acc + (2*p  )*4, ah0, ah1, ah2, ah3, bh0, bh1);
                MMA_BF16(acc + (2*p  )*4, al0, al1, al2, al3, bh0, bh1);
                MMA_BF16(acc + (2*p  )*4, ah0, ah1, ah2, ah3, bl0, bl1);
                MMA_BF16(acc + (2*p+1)*4, ah0, ah1, ah2, ah3, bh2, bh3);
                MMA_BF16(acc + (2*p+1)*4, al0, al1, al2, al3, bh2, bh3);
                MMA_BF16(acc + (2*p+1)*4, ah0, ah1, ah2, ah3, bl2, bl3);
            }
        }

        const int r0 = w * 16 + (L >> 2);
        if (Layer < 3) {
            #pragma unroll
            for (int nt = 0; nt < 16; ++nt) {
                int c = nt * 8 + p2;
                float s[4];
                #pragma unroll
                for (int j = 0; j < 4; ++j) {
                    float v = acc[nt*4 + j];
                    s[j] = v / (1.f + __expf(-v));
                }
                uint32_t h0, l0, h1, l1;
                hilo2(s[0], s[1], h0, l0);
                hilo2(s[2], s[3], h1, l1);
                uint32_t o0 = (uint32_t)(r0 * ST + c) * 2;
                uint32_t o1 = (uint32_t)((r0 + 8) * ST + c) * 2;
                asm volatile("st.shared.b32 [%0], %1;" :: "r"(sb + SM_A_HI + o0), "r"(h0));
                asm volatile("st.shared.b32 [%0], %1;" :: "r"(sb + SM_A_LO + o0), "r"(l0));
                asm volatile("st.shared.b32 [%0], %1;" :: "r"(sb + SM_A_HI + o1), "r"(h1));
                asm volatile("st.shared.b32 [%0], %1;" :: "r"(sb + SM_A_LO + o1), "r"(l1));
            }
            __syncthreads();
            convert_W(sb, Wn[Layer], w, L);
            __syncthreads();
        } else {
            int gr0 = row0 + r0;
            int gr1 = gr0 + 8;
            #pragma unroll
            for (int nt = 0; nt < 16; ++nt) {
                int c = nt * 8 + p2;
                if (gr0 < N_NODES)
                    *(float2*)(out + (size_t)gr0 * 128 + c) =
                        make_float2(acc[nt*4 + 0], acc[nt*4 + 1]);
                if (gr1 < N_NODES)
                    *(float2*)(out + (size_t)gr1 * 128 + c) =
                        make_float2(acc[nt*4 + 2], acc[nt*4 + 3]);
            }
        }
    }
}

// ---------------------------------------------------------------------------
// Launch: zero+detect -> hist -> scan1 -> scan23 -> scatter -> gather -> MLP
// ---------------------------------------------------------------------------
extern "C" void kernel_launch(void* const* d_in, const int* in_sizes, int n_in,
                              void* d_out, int out_size) {
    const float* x     = (const float*)d_in[0];
    const float* rbf   = (const float*)d_in[1];
    const void*  idx   = d_in[2];
    const float* W_rbf = (const float*)d_in[3];
    const float* W1    = (const float*)d_in[4];
    const float* b1    = (const float*)d_in[5];
    const float* W2    = (const float*)d_in[6];
    const float* b2    = (const float*)d_in[7];
    const float* W3    = (const float*)d_in[8];
    const float* b3    = (const float*)d_in[9];
    const float* W_out = (const float*)d_in[10];
    float* out = (float*)d_out;

    const int E = in_sizes[0] / HID;

    float* bufA = nullptr;
    cudaGetSymbolAddress((void**)&bufA, g_bufA);

    cudaFuncSetAttribute(mlp_fused_kernel,
                         cudaFuncAttributeMaxDynamicSharedMemorySize, SMEM_TOT);

    zero_detect_kernel<<<128, 256>>>((const int*)idx);
    hist_kernel<<<4096, 256>>>(idx, E);
    scan1_kernel<<<NB_SCAN, 1024>>>();
    scan23_kernel<<<(N_NODES + 255) / 256, 256>>>(E);
    scatter_kernel<<<4096, 256>>>(idx, E);
    gather_kernel<<<N_NODES / 8, 256>>>(x, rbf, W_rbf, bufA);

    const int gtiles = (N_NODES + 255) / 256;
    mlp_fused_kernel<<<gtiles, 512, SMEM_TOT>>>(bufA, W1, b1, W2, b2, W3, b3,
                                                W_out, out);
}